// round 5
// baseline (speedup 1.0000x reference)
#include <cuda_runtime.h>

// QAttentionLayer: out[..., i] = cumprod_{j<=i}( cos(x_j) * cos(w_j) )
// x: [16384, 256, 10] fp32. Rows of 10 floats; lcm(10,4)=20 -> 5-lane groups,
// each lane owns ONE contiguous float4 (perfect coalescing), cross-lane prefix
// product via 2 SHFL.IDX. ILP=8 front-batched LDG.128 (MLP_p1=8).
// Tail-peeled: only the single final warp takes the bounds-checked path; all
// other warps run a branchless uniform path. Streaming cache hints.

#define NQ  10
#define ILP 8
#define GPW (6 * ILP)   // groups per warp = 48

struct LaneCtx {
    float cw0, cw1, cw2, cw3;
    int k, srcA, srcB;
    bool r2;
};

__device__ __forceinline__ LaneCtx make_ctx(int lane, const float* __restrict__ w)
{
    LaneCtx c;
    int gw = lane / 5;
    c.k = lane - gw * 5;
    int base = lane - c.k;
    int p = 4 * c.k;
    int q0 = (p     < NQ) ? p     : p - NQ;
    int q1 = (p + 1 < NQ) ? p + 1 : p + 1 - NQ;
    int q2 = (p + 2 < NQ) ? p + 2 : p + 2 - NQ;
    int q3 = (p + 3 < NQ) ? p + 3 : p + 3 - NQ;
    c.cw0 = __cosf(__ldg(&w[q0]));
    c.cw1 = __cosf(__ldg(&w[q1]));
    c.cw2 = __cosf(__ldg(&w[q2]));
    c.cw3 = __cosf(__ldg(&w[q3]));
    c.r2   = (c.k == 2);
    c.srcA = base + ((c.k >= 3) ? 2 : 0);
    c.srcB = base + ((c.k == 4) ? 3 : 1);
    return c;
}

__device__ __forceinline__ float4 scan20(const LaneCtx& c, float4 a)
{
    float c0 = __cosf(a.x) * c.cw0;
    float c1 = __cosf(a.y) * c.cw1;
    float c2 = __cosf(a.z) * c.cw2;
    float c3 = __cosf(a.w) * c.cw3;

    // Local segmented inclusive scan (row reset at p=10 -> k==2, j==2)
    float lp0 = c0;
    float lp1 = lp0 * c1;
    float lp2 = c.r2 ? c2 : lp1 * c2;
    float lp3 = lp2 * c3;

    // Cross-lane exclusive prefix (2 IDX shuffles)
    float sA = __shfl_sync(0xffffffffu, lp3, c.srcA);
    float sB = __shfl_sync(0xffffffffu, lp3, c.srcB);
    float pre = (c.k == 0) ? 1.0f
              : (c.k == 1 || c.k == 3) ? sA
              : sA * sB;
    float pre_hi = c.r2 ? 1.0f : pre;

    float4 r;
    r.x = lp0 * pre;
    r.y = lp1 * pre;
    r.z = lp2 * pre_hi;
    r.w = lp3 * pre_hi;
    return r;
}

__global__ __launch_bounds__(512)
void qattn_main(const float4* __restrict__ x4,
                float4* __restrict__ o4,
                const float* __restrict__ w,
                int n_groups, int full_warps)
{
    int tid  = blockIdx.x * blockDim.x + threadIdx.x;
    int warp = tid >> 5;
    int lane = tid & 31;
    int gw   = lane / 5;                 // 0..6 (6 => idle lane 30/31)
    bool lane_ok = (gw < 6);

    if (warp > full_warps) return;

    LaneCtx c = make_ctx(lane, w);
    int g0 = warp * GPW + gw;            // first group handled by this lane

    if (warp < full_warps) {
        // ---- uniform fast path: no bounds checks ----
        if (!lane_ok) {
            // idle lanes still participate in shuffles below? No: shuffles only
            // read lanes < 30; idle lanes must still execute shfl for sync.
            float4 z = make_float4(0.f, 0.f, 0.f, 0.f);
#pragma unroll
            for (int it = 0; it < ILP; it++) scan20(c, z);
            return;
        }
        float4 a[ILP];
        int base4 = g0 * 5 + c.k;
#pragma unroll
        for (int it = 0; it < ILP; it++)
            a[it] = __ldcs(&x4[base4 + it * 30]);
#pragma unroll
        for (int it = 0; it < ILP; it++) {
            float4 r = scan20(c, a[it]);
            __stcs(&o4[base4 + it * 30], r);
        }
    } else {
        // ---- tail warp: bounds-checked ----
        float4 z = make_float4(0.f, 0.f, 0.f, 0.f);
#pragma unroll
        for (int it = 0; it < ILP; it++) {
            int g = g0 + it * 6;
            bool act = lane_ok && (g < n_groups);
            int idx = g * 5 + c.k;
            float4 a = act ? __ldcs(&x4[idx]) : z;
            float4 r = scan20(c, a);
            if (act) __stcs(&o4[idx], r);
        }
    }
}

extern "C" void kernel_launch(void* const* d_in, const int* in_sizes, int n_in,
                              void* d_out, int out_size)
{
    const float* x = (const float*)d_in[0];   // [16384*256*10] fp32
    const float* w = (const float*)d_in[1];   // [10] fp32
    float* out = (float*)d_out;

    long long total = (long long)in_sizes[0];   // 41,943,040 floats
    int n_groups    = (int)(total / 20);        // 2,097,152 groups of 20 floats
    int full_warps  = n_groups / GPW;           // 43,690 (tail: 32 groups)
    int tail_groups = n_groups - full_warps * GPW;
    int n_warps     = full_warps + (tail_groups ? 1 : 0);

    long long threads = (long long)n_warps * 32;
    int block = 512;
    long long grid = (threads + block - 1) / block;

    qattn_main<<<(unsigned)grid, block>>>(reinterpret_cast<const float4*>(x),
                                          reinterpret_cast<float4*>(out),
                                          w, n_groups, full_warps);
}

// round 6
// speedup vs baseline: 1.1071x; 1.1071x over previous
#include <cuda_runtime.h>

// QAttentionLayer: out[..., i] = cumprod_{j<=i}( cos(x_j) * cos(w_j) )
// x: [16384, 256, 10] fp32. Rows of 10 floats; lcm(10,4)=20 -> 5-lane groups,
// each lane owns ONE contiguous float4 (perfect coalescing), cross-lane prefix
// product via 2 SHFL.IDX. ILP=8: 8 front-batched LDG.128 per thread (MLP_p1=8).
// Single uniform code path, per-lane predication (no divergent specialization —
// R5 showed control-flow splitting regresses). act/idx recomputed instead of
// carried in register arrays.

#define NQ  10
#define ILP 8

__global__ __launch_bounds__(256)
void qattn_main(const float4* __restrict__ x4,
                float4* __restrict__ o4,
                const float* __restrict__ w,
                int n_groups)
{
    int tid  = blockIdx.x * blockDim.x + threadIdx.x;
    int warp = tid >> 5;
    int lane = tid & 31;
    int gw   = lane / 5;          // group slot within warp tile: 0..6 (6 => idle)
    int k    = lane - gw * 5;     // float4 slot within group: 0..4
    int base = lane - k;          // first lane of this 5-lane group
    bool lane_ok = (gw < 6);

    // Weight cosines for positions p = 4k..4k+3 (q = p mod 10), computed once.
    float cw0, cw1, cw2, cw3;
    {
        int p = 4 * k;
        int q0 = (p     < NQ) ? p     : p - NQ;
        int q1 = (p + 1 < NQ) ? p + 1 : p + 1 - NQ;
        int q2 = (p + 2 < NQ) ? p + 2 : p + 2 - NQ;
        int q3 = (p + 3 < NQ) ? p + 3 : p + 3 - NQ;
        cw0 = __cosf(__ldg(&w[q0]));
        cw1 = __cosf(__ldg(&w[q1]));
        cw2 = __cosf(__ldg(&w[q2]));
        cw3 = __cosf(__ldg(&w[q3]));
    }

    bool r2 = (k == 2);                          // in-thread row boundary lane
    int srcA = base + ((k >= 3) ? 2 : 0);
    int srcB = base + ((k == 4) ? 3 : 1);

    int g0    = warp * (6 * ILP) + gw;           // first group of this lane
    int base4 = g0 * 5 + k;                      // its float4 index

    float4 a[ILP];
    // Front-batch ALL loads: MLP = ILP. Predicated, single path.
#pragma unroll
    for (int it = 0; it < ILP; it++) {
        bool act = lane_ok && (g0 + it * 6 < n_groups);
        a[it] = act ? __ldcs(&x4[base4 + it * 30])
                    : make_float4(0.f, 0.f, 0.f, 0.f);
    }

#pragma unroll
    for (int it = 0; it < ILP; it++) {
        float c0 = __cosf(a[it].x) * cw0;
        float c1 = __cosf(a[it].y) * cw1;
        float c2 = __cosf(a[it].z) * cw2;
        float c3 = __cosf(a[it].w) * cw3;

        // Local segmented inclusive scan (reset at p=10 -> k==2, j==2)
        float lp0 = c0;
        float lp1 = lp0 * c1;
        float lp2 = r2 ? c2 : lp1 * c2;
        float lp3 = lp2 * c3;

        // Cross-lane exclusive prefix (2 IDX shuffles)
        float sA = __shfl_sync(0xffffffffu, lp3, srcA);
        float sB = __shfl_sync(0xffffffffu, lp3, srcB);
        float pre = (k == 0) ? 1.0f
                  : (k == 1 || k == 3) ? sA
                  : sA * sB;
        float pre_hi = r2 ? 1.0f : pre;

        float4 r;
        r.x = lp0 * pre;
        r.y = lp1 * pre;
        r.z = lp2 * pre_hi;
        r.w = lp3 * pre_hi;

        bool act = lane_ok && (g0 + it * 6 < n_groups);
        if (act) __stcs(&o4[base4 + it * 30], r);
    }
}

extern "C" void kernel_launch(void* const* d_in, const int* in_sizes, int n_in,
                              void* d_out, int out_size)
{
    const float* x = (const float*)d_in[0];   // [16384*256*10] fp32
    const float* w = (const float*)d_in[1];   // [10] fp32
    float* out = (float*)d_out;

    long long total = (long long)in_sizes[0];   // 41,943,040 floats
    int n_groups    = (int)(total / 20);        // 2,097,152 groups of 20 floats
    long long warps = ((long long)n_groups + 6 * ILP - 1) / (6 * ILP);
    long long threads = warps * 32;
    int block = 256;
    long long grid = (threads + block - 1) / block;

    qattn_main<<<(unsigned)grid, block>>>(reinterpret_cast<const float4*>(x),
                                          reinterpret_cast<float4*>(out),
                                          w, n_groups);
}